// round 11
// baseline (speedup 1.0000x reference)
#include <cuda_runtime.h>
#include <cuda_bf16.h>
#include <math.h>
#include <stdint.h>

#define BB 4
#define SS 2048
#define DDIM 1024
#define HH 16
#define RR (BB*SS)          /* 8192 rows */

// ---------------- scratch (static device arrays; no cudaMalloc) -------------
__device__ __nv_bfloat16 g_ahi[(size_t)RR * DDIM];               // 16 MB
__device__ __nv_bfloat16 g_alo[(size_t)RR * DDIM];               // 16 MB
__device__ __nv_bfloat16 g_mhi[(size_t)RR * 4 * DDIM];           // 64 MB (also QKV)
__device__ __nv_bfloat16 g_mlo[(size_t)RR * 4 * DDIM];           // 64 MB
__device__ __nv_bfloat16 g_bhi[4u * 1024u * 1024u];              // 8 MB
__device__ __nv_bfloat16 g_blo[4u * 1024u * 1024u];              // 8 MB

// ---------------- helpers ----------------------------------------------------
#define SWZ(o) ((uint32_t)(o) ^ (((uint32_t)(o) >> 3) & 0x70u))

__device__ __forceinline__ void cp_async16(uint32_t dst, const void* src) {
    asm volatile("cp.async.cg.shared.global [%0], [%1], 16;" :: "r"(dst), "l"(src));
}
__device__ __forceinline__ void cp_commit() {
    asm volatile("cp.async.commit_group;" ::: "memory");
}
template <int N> __device__ __forceinline__ void cp_wait() {
    asm volatile("cp.async.wait_group %0;" :: "n"(N) : "memory");
}
__device__ __forceinline__ void ldsm4(uint32_t &r0, uint32_t &r1, uint32_t &r2,
                                      uint32_t &r3, uint32_t addr) {
    asm volatile("ldmatrix.sync.aligned.m8n8.x4.shared.b16 {%0,%1,%2,%3}, [%4];"
        : "=r"(r0), "=r"(r1), "=r"(r2), "=r"(r3) : "r"(addr));
}
__device__ __forceinline__ void ldsm4t(uint32_t &r0, uint32_t &r1, uint32_t &r2,
                                       uint32_t &r3, uint32_t addr) {
    asm volatile("ldmatrix.sync.aligned.m8n8.x4.trans.shared.b16 {%0,%1,%2,%3}, [%4];"
        : "=r"(r0), "=r"(r1), "=r"(r2), "=r"(r3) : "r"(addr));
}
__device__ __forceinline__ void mma16816(float* d, uint32_t a0, uint32_t a1,
                                         uint32_t a2, uint32_t a3,
                                         uint32_t b0, uint32_t b1) {
    asm volatile(
        "mma.sync.aligned.m16n8k16.row.col.f32.bf16.bf16.f32 "
        "{%0,%1,%2,%3}, {%4,%5,%6,%7}, {%8,%9}, {%0,%1,%2,%3};"
        : "+f"(d[0]), "+f"(d[1]), "+f"(d[2]), "+f"(d[3])
        : "r"(a0), "r"(a1), "r"(a2), "r"(a3), "r"(b0), "r"(b1));
}
__device__ __forceinline__ void split2(float x, float y,
                                       __nv_bfloat162 &h2, __nv_bfloat162 &l2) {
    __nv_bfloat16 hx = __float2bfloat16(x), hy = __float2bfloat16(y);
    h2 = __halves2bfloat162(hx, hy);
    l2 = __halves2bfloat162(__float2bfloat16(x - __bfloat162float(hx)),
                            __float2bfloat16(y - __bfloat162float(hy)));
}
__device__ __forceinline__ uint32_t packbf(float x, float y) {
    __nv_bfloat162 t = __halves2bfloat162(__float2bfloat16(x), __float2bfloat16(y));
    return *(uint32_t*)&t;
}
__device__ __forceinline__ float gelu_f(float v) {
    const float c = 0.7978845608028654f;
    float t = tanhf(c * (v + 0.044715f * v * v * v));
    return v * 0.5f * (1.0f + t);
}

// ---------------- LayerNorm fused with bf16 hi/lo split ----------------------
__global__ __launch_bounds__(256) void ln_split_kernel(
    const float* __restrict__ x, const float* __restrict__ gw,
    const float* __restrict__ sw, __nv_bfloat16* __restrict__ hi,
    __nv_bfloat16* __restrict__ lo)
{
    int row = blockIdx.x;
    int tid = threadIdx.x;
    const float4* xr = (const float4*)(x + (size_t)row * DDIM);
    float4 xv = xr[tid];
    float sum = xv.x + xv.y + xv.z + xv.w;
    float sq  = xv.x*xv.x + xv.y*xv.y + xv.z*xv.z + xv.w*xv.w;
    #pragma unroll
    for (int o = 16; o > 0; o >>= 1) {
        sum += __shfl_down_sync(0xffffffffu, sum, o);
        sq  += __shfl_down_sync(0xffffffffu, sq,  o);
    }
    __shared__ float rs[8], rq[8], bmean, brstd;
    int wid = tid >> 5, lid = tid & 31;
    if (lid == 0) { rs[wid] = sum; rq[wid] = sq; }
    __syncthreads();
    if (wid == 0) {
        float s2 = (lid < 8) ? rs[lid] : 0.f;
        float q2 = (lid < 8) ? rq[lid] : 0.f;
        #pragma unroll
        for (int o = 4; o > 0; o >>= 1) {
            s2 += __shfl_down_sync(0xffffffffu, s2, o);
            q2 += __shfl_down_sync(0xffffffffu, q2, o);
        }
        if (lid == 0) {
            float mean = s2 * (1.0f / DDIM);
            float var  = q2 * (1.0f / DDIM) - mean * mean;
            bmean = mean; brstd = rsqrtf(var + 1e-5f);
        }
    }
    __syncthreads();
    float mean = bmean, rstd = brstd;
    float4 gv = ((const float4*)gw)[tid];
    float4 sv = ((const float4*)sw)[tid];
    float o0 = gv.x * ((xv.x - mean) * rstd) + sv.x;
    float o1 = gv.y * ((xv.y - mean) * rstd) + sv.y;
    float o2 = gv.z * ((xv.z - mean) * rstd) + sv.z;
    float o3 = gv.w * ((xv.w - mean) * rstd) + sv.w;
    __nv_bfloat162 h2a, l2a, h2b, l2b;
    split2(o0, o1, h2a, l2a);
    split2(o2, o3, h2b, l2b);
    __nv_bfloat162* hp = (__nv_bfloat162*)(hi + (size_t)row * DDIM);
    __nv_bfloat162* lp = (__nv_bfloat162*)(lo + (size_t)row * DDIM);
    hp[2*tid] = h2a; hp[2*tid+1] = h2b;
    lp[2*tid] = l2a; lp[2*tid+1] = l2b;
}

// ---------------- weight transpose + split: W[K,N] -> out[N,K] hi/lo --------
__global__ __launch_bounds__(256) void cvt_t_kernel(
    const float* __restrict__ W, __nv_bfloat16* __restrict__ hi,
    __nv_bfloat16* __restrict__ lo, int K, int N)
{
    __shared__ float t[32][33];
    int n0 = blockIdx.x * 32, k0 = blockIdx.y * 32;
    int tx = threadIdx.x & 31, ty = threadIdx.x >> 5;   // 32 x 8
    #pragma unroll
    for (int i = 0; i < 4; i++)
        t[ty + 8*i][tx] = W[(size_t)(k0 + ty + 8*i) * N + n0 + tx];
    __syncthreads();
    #pragma unroll
    for (int i = 0; i < 4; i++) {
        float v = t[tx][ty + 8*i];
        size_t o = (size_t)(n0 + ty + 8*i) * K + k0 + tx;
        __nv_bfloat16 h = __float2bfloat16(v);
        hi[o] = h;
        lo[o] = __float2bfloat16(v - __bfloat162float(h));
    }
}

// ---------------- warp-MMA bf16 GEMM, fused 3-combo split --------------------
// C[M,N] = Ahi*Bhi + Ahi*Blo + Alo*Bhi. Single K loop; each BK=32 stage holds
// Ahi|Alo|Bhi|Blo tiles (32KB). 128x128 tile, 8 warps (64x32), 4 stages.
#define TG_STAGE 32768
#define TG_SMEM (4 * TG_STAGE)

template <bool BIAS, bool GELU, bool RES, bool SPL, bool QKV>
__global__ __launch_bounds__(256) void tgemm_kernel(
    const __nv_bfloat16* __restrict__ Ahi, const __nv_bfloat16* __restrict__ Alo,
    const __nv_bfloat16* __restrict__ Bhi, const __nv_bfloat16* __restrict__ Blo,
    const float* __restrict__ bias, const float* __restrict__ res,
    float* __restrict__ C, __nv_bfloat16* __restrict__ Chi,
    __nv_bfloat16* __restrict__ Clo, int M, int N, int K)
{
    extern __shared__ char smem[];
    uint32_t sb = (uint32_t)__cvta_generic_to_shared(smem);
    int tid = threadIdx.x, lane = tid & 31, wid = tid >> 5;
    int wm = wid & 1, wn = wid >> 1;
    size_t row0 = (size_t)blockIdx.y * 128;
    size_t col0 = (size_t)blockIdx.x * 128;
    const int kc = K >> 5;

    float acc[4][4][4];
    #pragma unroll
    for (int i = 0; i < 4; i++)
        #pragma unroll
        for (int j = 0; j < 4; j++)
            #pragma unroll
            for (int r = 0; r < 4; r++) acc[i][j][r] = 0.f;

    int rowA = wm * 64 + (lane & 15);
    uint32_t xvA = (uint32_t)((rowA >> 1) & 3);
    int hiA = lane >> 4;
    int nrow = wn * 32 + (lane & 7) + ((lane & 16) >> 1);
    uint32_t xvB = (uint32_t)((nrow >> 1) & 3);
    int hiB = (lane >> 3) & 1;

    // per-thread load coords: 512 16B-ops per 8KB tile, 2 per thread per tile
    int lr0 = tid >> 1, lc0 = (tid & 1) << 1;     // rows 0..127, ck {0,2}
    auto tile_off = [&](int r, int ck) -> uint32_t {
        return (uint32_t)(r * 64 + ((ck ^ ((r >> 1) & 3)) << 4));
    };

    auto load_chunk = [&](int c) {
        if (c < kc) {
            int k0 = c << 5;
            uint32_t st = sb + (c & 3) * TG_STAGE;
            const __nv_bfloat16* Ah = Ahi + (row0 + lr0) * K + k0;
            const __nv_bfloat16* Al = Alo + (row0 + lr0) * K + k0;
            const __nv_bfloat16* Bh = Bhi + (col0 + lr0) * K + k0;
            const __nv_bfloat16* Bl = Blo + (col0 + lr0) * K + k0;
            #pragma unroll
            for (int i = 0; i < 2; i++) {
                int ck = lc0 + i;
                uint32_t off = tile_off(lr0, ck);
                cp_async16(st + off,          Ah + ck * 8);
                cp_async16(st + 8192  + off,  Al + ck * 8);
                cp_async16(st + 16384 + off,  Bh + ck * 8);
                cp_async16(st + 24576 + off,  Bl + ck * 8);
            }
        }
        cp_commit();
    };

    load_chunk(0); load_chunk(1); load_chunk(2);

    for (int c = 0; c < kc; c++) {
        cp_wait<2>();
        __syncthreads();
        load_chunk(c + 3);
        uint32_t st = sb + (c & 3) * TG_STAGE;
        #pragma unroll
        for (int ks = 0; ks < 2; ks++) {
            uint32_t ah[4][4], al[4][4], bh[4][2], bl[4][2];
            uint32_t ckA = ((uint32_t)(2*ks + hiA)) ^ xvA;
            uint32_t ckB = ((uint32_t)(2*ks + hiB)) ^ xvB;
            #pragma unroll
            for (int mt = 0; mt < 4; mt++) {
                uint32_t ro = (uint32_t)((rowA + mt*16) * 64) + (ckA << 4);
                ldsm4(ah[mt][0], ah[mt][1], ah[mt][2], ah[mt][3], st + ro);
                ldsm4(al[mt][0], al[mt][1], al[mt][2], al[mt][3], st + 8192 + ro);
            }
            #pragma unroll
            for (int np = 0; np < 2; np++) {
                uint32_t ro = (uint32_t)((nrow + np*16) * 64) + (ckB << 4);
                ldsm4(bh[np*2][0], bh[np*2][1], bh[np*2+1][0], bh[np*2+1][1],
                      st + 16384 + ro);
                ldsm4(bl[np*2][0], bl[np*2][1], bl[np*2+1][0], bl[np*2+1][1],
                      st + 24576 + ro);
            }
            #pragma unroll
            for (int mt = 0; mt < 4; mt++)
                #pragma unroll
                for (int nt = 0; nt < 4; nt++) {
                    mma16816(acc[mt][nt], ah[mt][0], ah[mt][1], ah[mt][2], ah[mt][3],
                             bh[nt][0], bh[nt][1]);
                    mma16816(acc[mt][nt], ah[mt][0], ah[mt][1], ah[mt][2], ah[mt][3],
                             bl[nt][0], bl[nt][1]);
                    mma16816(acc[mt][nt], al[mt][0], al[mt][1], al[mt][2], al[mt][3],
                             bh[nt][0], bh[nt][1]);
                }
        }
    }

    // ---------------- epilogue ----------------
    size_t rbase = row0 + wm*64 + (lane >> 2);
    size_t cbase = col0 + wn*32 + (lane & 3) * 2;
    #pragma unroll
    for (int mt = 0; mt < 4; mt++) {
        #pragma unroll
        for (int h = 0; h < 2; h++) {
            size_t r = rbase + mt*16 + h*8;
            #pragma unroll
            for (int nt = 0; nt < 4; nt++) {
                size_t cidx = cbase + nt*8;
                float v0 = acc[mt][nt][2*h], v1 = acc[mt][nt][2*h+1];
                if (BIAS) {
                    float2 bv = *(const float2*)(bias + cidx);
                    v0 += bv.x; v1 += bv.y;
                }
                if (GELU) { v0 = gelu_f(v0); v1 = gelu_f(v1); }
                if (RES) {
                    float2 rv = *(const float2*)(res + r * N + cidx);
                    v0 += rv.x; v1 += rv.y;
                }
                if (QKV) {
                    int sec = (int)(cidx >> 10);
                    int hh  = ((int)cidx >> 6) & 15;
                    int d   = (int)cidx & 63;
                    int b   = (int)(r >> 11);
                    int s   = (int)(r & 2047);
                    if (sec == 0) { v0 *= 0.125f; v1 *= 0.125f; }
                    __nv_bfloat16* dst = Chi + (size_t)sec * RR * DDIM +
                        (((size_t)(b * HH + hh) * SS + s) << 6) + d;
                    *(__nv_bfloat162*)dst =
                        __halves2bfloat162(__float2bfloat16(v0), __float2bfloat16(v1));
                } else if (SPL) {
                    __nv_bfloat162 h2, l2;
                    split2(v0, v1, h2, l2);
                    *(__nv_bfloat162*)(Chi + r * N + cidx) = h2;
                    *(__nv_bfloat162*)(Clo + r * N + cidx) = l2;
                } else {
                    float2 o; o.x = v0; o.y = v1;
                    *(float2*)(C + r * N + cidx) = o;
                }
            }
        }
    }
}

// ---------------- tensor-core flash attention --------------------------------
__global__ __launch_bounds__(128) void attn_kernel(
    const __nv_bfloat16* __restrict__ Qg, const __nv_bfloat16* __restrict__ Kg,
    const __nv_bfloat16* __restrict__ Vg, __nv_bfloat16* __restrict__ chi,
    __nv_bfloat16* __restrict__ clo)
{
    __shared__ __align__(128) char smQ[64 * 128];
    __shared__ __align__(128) char smK[2][64 * 128];
    __shared__ __align__(128) char smV[2][64 * 128];

    int qt = blockIdx.x, h = blockIdx.y, b = blockIdx.z;
    int tid = threadIdx.x, lane = tid & 31, w = tid >> 5;

    size_t headbase = (size_t)(b * HH + h) * SS * 64;
    const __nv_bfloat16* Qh = Qg + headbase + (size_t)qt * 64 * 64;
    const __nv_bfloat16* Kh = Kg + headbase;
    const __nv_bfloat16* Vh = Vg + headbase;

    uint32_t sq  = (uint32_t)__cvta_generic_to_shared(smQ);
    uint32_t sk[2] = { (uint32_t)__cvta_generic_to_shared(smK[0]),
                       (uint32_t)__cvta_generic_to_shared(smK[1]) };
    uint32_t sv[2] = { (uint32_t)__cvta_generic_to_shared(smV[0]),
                       (uint32_t)__cvta_generic_to_shared(smV[1]) };

    #pragma unroll
    for (int i = 0; i < 4; i++) {
        int idx = tid + 128 * i;
        int r = idx >> 3, c = idx & 7;
        cp_async16(sq + SWZ(r * 128 + c * 16), Qh + r * 64 + c * 8);
    }
    auto load_kv = [&](int kt) {
        int st = kt & 1;
        const __nv_bfloat16* Kc = Kh + (size_t)kt * 64 * 64;
        const __nv_bfloat16* Vc = Vh + (size_t)kt * 64 * 64;
        #pragma unroll
        for (int i = 0; i < 4; i++) {
            int idx = tid + 128 * i;
            int r = idx >> 3, c = idx & 7;
            uint32_t off = SWZ(r * 128 + c * 16);
            cp_async16(sk[st] + off, Kc + r * 64 + c * 8);
            cp_async16(sv[st] + off, Vc + r * 64 + c * 8);
        }
        cp_commit();
    };
    load_kv(0);
    cp_wait<0>();
    __syncthreads();

    uint32_t qf[4][4];
    {
        int rowA = w * 16 + (lane & 15);
        #pragma unroll
        for (int dt = 0; dt < 4; dt++)
            ldsm4(qf[dt][0], qf[dt][1], qf[dt][2], qf[dt][3],
                  sq + SWZ(rowA * 128 + dt * 32 + (lane >> 4) * 16));
    }

    float acc[8][4];
    #pragma unroll
    for (int nt = 0; nt < 8; nt++)
        #pragma unroll
        for (int r = 0; r < 4; r++) acc[nt][r] = 0.f;
    float mrow[2] = { -INFINITY, -INFINITY };
    float lrow[2] = { 0.f, 0.f };

    for (int kt = 0; kt <= qt; kt++) {
        int st = kt & 1;
        if (kt < qt) load_kv(kt + 1);
        if (kt < qt) cp_wait<1>(); else cp_wait<0>();
        __syncthreads();

        float s[8][4];
        #pragma unroll
        for (int nt = 0; nt < 8; nt++)
            #pragma unroll
            for (int r = 0; r < 4; r++) s[nt][r] = 0.f;
        int krow = (lane & 7) + ((lane & 16) >> 1);
        int khi  = (lane >> 3) & 1;
        #pragma unroll
        for (int dt = 0; dt < 4; dt++) {
            uint32_t kb[8][2];
            #pragma unroll
            for (int np = 0; np < 4; np++)
                ldsm4(kb[np*2][0], kb[np*2][1], kb[np*2+1][0], kb[np*2+1][1],
                      sk[st] + SWZ((np*16 + krow) * 128 + dt*32 + khi*16));
            #pragma unroll
            for (int nt = 0; nt < 8; nt++)
                mma16816(s[nt], qf[dt][0], qf[dt][1], qf[dt][2], qf[dt][3],
                         kb[nt][0], kb[nt][1]);
        }

        if (kt == qt) {
            #pragma unroll
            for (int nt = 0; nt < 8; nt++)
                #pragma unroll
                for (int r = 0; r < 4; r++) {
                    int qr = w*16 + (lane >> 2) + (r >> 1) * 8;
                    int kc2 = nt*8 + (lane & 3)*2 + (r & 1);
                    if (kc2 > qr) s[nt][r] = -INFINITY;
                }
        }

        #pragma unroll
        for (int hh = 0; hh < 2; hh++) {
            float mx = -INFINITY;
            #pragma unroll
            for (int nt = 0; nt < 8; nt++) {
                mx = fmaxf(mx, s[nt][2*hh]);
                mx = fmaxf(mx, s[nt][2*hh+1]);
            }
            mx = fmaxf(mx, __shfl_xor_sync(0xffffffffu, mx, 1));
            mx = fmaxf(mx, __shfl_xor_sync(0xffffffffu, mx, 2));
            float mnew = fmaxf(mrow[hh], mx);
            float corr = __expf(mrow[hh] - mnew);
            mrow[hh] = mnew;
            float psum = 0.f;
            #pragma unroll
            for (int nt = 0; nt < 8; nt++) {
                float p0 = __expf(s[nt][2*hh]   - mnew);
                float p1 = __expf(s[nt][2*hh+1] - mnew);
                s[nt][2*hh] = p0; s[nt][2*hh+1] = p1;
                psum += p0 + p1;
            }
            psum += __shfl_xor_sync(0xffffffffu, psum, 1);
            psum += __shfl_xor_sync(0xffffffffu, psum, 2);
            lrow[hh] = lrow[hh] * corr + psum;
            #pragma unroll
            for (int nt = 0; nt < 8; nt++) {
                acc[nt][2*hh]   *= corr;
                acc[nt][2*hh+1] *= corr;
            }
        }

        #pragma unroll
        for (int kt2 = 0; kt2 < 4; kt2++) {
            uint32_t a0 = packbf(s[2*kt2][0],   s[2*kt2][1]);
            uint32_t a1 = packbf(s[2*kt2][2],   s[2*kt2][3]);
            uint32_t a2 = packbf(s[2*kt2+1][0], s[2*kt2+1][1]);
            uint32_t a3 = packbf(s[2*kt2+1][2], s[2*kt2+1][3]);
            uint32_t vb[8][2];
            #pragma unroll
            for (int np = 0; np < 4; np++)
                ldsm4t(vb[np*2][0], vb[np*2][1], vb[np*2+1][0], vb[np*2+1][1],
                       sv[st] + SWZ((kt2*16 + (lane & 15)) * 128 + np*32 + (lane >> 4)*16));
            #pragma unroll
            for (int nt = 0; nt < 8; nt++)
                mma16816(acc[nt], a0, a1, a2, a3, vb[nt][0], vb[nt][1]);
        }
        __syncthreads();
    }

    #pragma unroll
    for (int hh = 0; hh < 2; hh++) {
        float inv = 1.f / lrow[hh];
        int row = qt*64 + w*16 + (lane >> 2) + hh*8;
        size_t obase = ((size_t)(b * SS + row)) * DDIM + h * 64;
        #pragma unroll
        for (int nt = 0; nt < 8; nt++) {
            int d = nt*8 + (lane & 3)*2;
            __nv_bfloat162 h2, l2;
            split2(acc[nt][2*hh] * inv, acc[nt][2*hh+1] * inv, h2, l2);
            *(__nv_bfloat162*)(chi + obase + d) = h2;
            *(__nv_bfloat162*)(clo + obase + d) = l2;
        }
    }
}

// ---------------- host launch ------------------------------------------------
extern "C" void kernel_launch(void* const* d_in, const int* in_sizes, int n_in,
                              void* d_out, int out_size)
{
    const float* x    = (const float*)d_in[0];
    const float* Wqkv = (const float*)d_in[1];
    const float* Wout = (const float*)d_in[2];
    const float* bout = (const float*)d_in[3];
    const float* W1   = (const float*)d_in[4];
    const float* b1   = (const float*)d_in[5];
    const float* W2   = (const float*)d_in[6];
    const float* b2   = (const float*)d_in[7];
    const float* g1   = (const float*)d_in[8];
    const float* s1   = (const float*)d_in[9];
    const float* g2   = (const float*)d_in[10];
    const float* s2   = (const float*)d_in[11];
    float* out = (float*)d_out;

    __nv_bfloat16 *pahi, *palo, *pmhi, *pmlo, *pbhi, *pblo;
    cudaGetSymbolAddress((void**)&pahi, g_ahi);
    cudaGetSymbolAddress((void**)&palo, g_alo);
    cudaGetSymbolAddress((void**)&pmhi, g_mhi);
    cudaGetSymbolAddress((void**)&pmlo, g_mlo);
    cudaGetSymbolAddress((void**)&pbhi, g_bhi);
    cudaGetSymbolAddress((void**)&pblo, g_blo);

    __nv_bfloat16* pQ = pmhi;                          // [B,H,S,64]
    __nv_bfloat16* pK = pmhi + (size_t)RR * DDIM;
    __nv_bfloat16* pV = pmhi + (size_t)2 * RR * DDIM;

    cudaFuncSetAttribute(tgemm_kernel<false,false,false,false,true>,
                         cudaFuncAttributeMaxDynamicSharedMemorySize, TG_SMEM);
    cudaFuncSetAttribute(tgemm_kernel<true,false,true,false,false>,
                         cudaFuncAttributeMaxDynamicSharedMemorySize, TG_SMEM);
    cudaFuncSetAttribute(tgemm_kernel<true,true,false,true,false>,
                         cudaFuncAttributeMaxDynamicSharedMemorySize, TG_SMEM);

    // 1. LN1 -> split(h)
    ln_split_kernel<<<RR, 256>>>(x, g1, s1, pahi, palo);
    // 2. qkv = h @ Wqkv -> bf16 Q(scaled)/K/V head-major
    cvt_t_kernel<<<dim3(3*DDIM/32, DDIM/32), 256>>>(Wqkv, pbhi, pblo, DDIM, 3*DDIM);
    tgemm_kernel<false,false,false,false,true><<<dim3(3*DDIM/128, RR/128), 256, TG_SMEM>>>(
        pahi, palo, pbhi, pblo, nullptr, nullptr, nullptr, pQ, nullptr,
        RR, 3*DDIM, DDIM);
    // 3. attention -> split(ctx)
    attn_kernel<<<dim3(SS/64, HH, BB), 128>>>(pQ, pK, pV, pahi, palo);
    // 4. out = x + ctx @ Wout + bout
    cvt_t_kernel<<<dim3(DDIM/32, DDIM/32), 256>>>(Wout, pbhi, pblo, DDIM, DDIM);
    tgemm_kernel<true,false,true,false,false><<<dim3(DDIM/128, RR/128), 256, TG_SMEM>>>(
        pahi, palo, pbhi, pblo, bout, x, out, nullptr, nullptr,
        RR, DDIM, DDIM);
    // 5. LN2 -> split(h)
    ln_split_kernel<<<RR, 256>>>(out, g2, s2, pahi, palo);
    // 6. mid = gelu(h @ W1 + b1) -> split(mid)
    cvt_t_kernel<<<dim3(4*DDIM/32, DDIM/32), 256>>>(W1, pbhi, pblo, DDIM, 4*DDIM);
    tgemm_kernel<true,true,false,true,false><<<dim3(4*DDIM/128, RR/128), 256, TG_SMEM>>>(
        pahi, palo, pbhi, pblo, b1, nullptr, nullptr, pmhi, pmlo,
        RR, 4*DDIM, DDIM);
    // 7. out = out + mid @ W2 + b2
    cvt_t_kernel<<<dim3(DDIM/32, 4*DDIM/32), 256>>>(W2, pbhi, pblo, 4*DDIM, DDIM);
    tgemm_kernel<true,false,true,false,false><<<dim3(DDIM/128, RR/128), 256, TG_SMEM>>>(
        pmhi, pmlo, pbhi, pblo, b2, out, out, nullptr, nullptr,
        RR, DDIM, 4*DDIM);
}

// round 12
// speedup vs baseline: 1.1457x; 1.1457x over previous
#include <cuda_runtime.h>
#include <cuda_bf16.h>
#include <math.h>
#include <stdint.h>

#define BB 4
#define SS 2048
#define DDIM 1024
#define HH 16
#define RR (BB*SS)          /* 8192 rows */

// ---------------- scratch (static device arrays; no cudaMalloc) -------------
__device__ __nv_bfloat16 g_ahi[(size_t)RR * DDIM];               // 16 MB
__device__ __nv_bfloat16 g_alo[(size_t)RR * DDIM];               // 16 MB
__device__ __nv_bfloat16 g_mhi[(size_t)RR * 4 * DDIM];           // 64 MB (also QKV)
__device__ __nv_bfloat16 g_mlo[(size_t)RR * 4 * DDIM];           // 64 MB
__device__ __nv_bfloat16 g_bhi[4u * 1024u * 1024u];              // 8 MB
__device__ __nv_bfloat16 g_blo[4u * 1024u * 1024u];              // 8 MB

// ---------------- helpers ----------------------------------------------------
#define SWZ(o) ((uint32_t)(o) ^ (((uint32_t)(o) >> 3) & 0x70u))

__device__ __forceinline__ void cp_async16(uint32_t dst, const void* src) {
    asm volatile("cp.async.cg.shared.global [%0], [%1], 16;" :: "r"(dst), "l"(src));
}
__device__ __forceinline__ void cp_commit() {
    asm volatile("cp.async.commit_group;" ::: "memory");
}
template <int N> __device__ __forceinline__ void cp_wait() {
    asm volatile("cp.async.wait_group %0;" :: "n"(N) : "memory");
}
__device__ __forceinline__ void ldsm4(uint32_t &r0, uint32_t &r1, uint32_t &r2,
                                      uint32_t &r3, uint32_t addr) {
    asm volatile("ldmatrix.sync.aligned.m8n8.x4.shared.b16 {%0,%1,%2,%3}, [%4];"
        : "=r"(r0), "=r"(r1), "=r"(r2), "=r"(r3) : "r"(addr));
}
__device__ __forceinline__ void ldsm4t(uint32_t &r0, uint32_t &r1, uint32_t &r2,
                                       uint32_t &r3, uint32_t addr) {
    asm volatile("ldmatrix.sync.aligned.m8n8.x4.trans.shared.b16 {%0,%1,%2,%3}, [%4];"
        : "=r"(r0), "=r"(r1), "=r"(r2), "=r"(r3) : "r"(addr));
}
__device__ __forceinline__ void mma16816(float* d, uint32_t a0, uint32_t a1,
                                         uint32_t a2, uint32_t a3,
                                         uint32_t b0, uint32_t b1) {
    asm volatile(
        "mma.sync.aligned.m16n8k16.row.col.f32.bf16.bf16.f32 "
        "{%0,%1,%2,%3}, {%4,%5,%6,%7}, {%8,%9}, {%0,%1,%2,%3};"
        : "+f"(d[0]), "+f"(d[1]), "+f"(d[2]), "+f"(d[3])
        : "r"(a0), "r"(a1), "r"(a2), "r"(a3), "r"(b0), "r"(b1));
}
__device__ __forceinline__ void split2(float x, float y,
                                       __nv_bfloat162 &h2, __nv_bfloat162 &l2) {
    __nv_bfloat16 hx = __float2bfloat16(x), hy = __float2bfloat16(y);
    h2 = __halves2bfloat162(hx, hy);
    l2 = __halves2bfloat162(__float2bfloat16(x - __bfloat162float(hx)),
                            __float2bfloat16(y - __bfloat162float(hy)));
}
__device__ __forceinline__ uint32_t packbf(float x, float y) {
    __nv_bfloat162 t = __halves2bfloat162(__float2bfloat16(x), __float2bfloat16(y));
    return *(uint32_t*)&t;
}
__device__ __forceinline__ float gelu_f(float v) {
    const float c = 0.7978845608028654f;
    float t = tanhf(c * (v + 0.044715f * v * v * v));
    return v * 0.5f * (1.0f + t);
}

// ---------------- LayerNorm fused with bf16 hi/lo split ----------------------
__global__ __launch_bounds__(256) void ln_split_kernel(
    const float* __restrict__ x, const float* __restrict__ gw,
    const float* __restrict__ sw, __nv_bfloat16* __restrict__ hi,
    __nv_bfloat16* __restrict__ lo)
{
    int row = blockIdx.x;
    int tid = threadIdx.x;
    const float4* xr = (const float4*)(x + (size_t)row * DDIM);
    float4 xv = xr[tid];
    float sum = xv.x + xv.y + xv.z + xv.w;
    float sq  = xv.x*xv.x + xv.y*xv.y + xv.z*xv.z + xv.w*xv.w;
    #pragma unroll
    for (int o = 16; o > 0; o >>= 1) {
        sum += __shfl_down_sync(0xffffffffu, sum, o);
        sq  += __shfl_down_sync(0xffffffffu, sq,  o);
    }
    __shared__ float rs[8], rq[8], bmean, brstd;
    int wid = tid >> 5, lid = tid & 31;
    if (lid == 0) { rs[wid] = sum; rq[wid] = sq; }
    __syncthreads();
    if (wid == 0) {
        float s2 = (lid < 8) ? rs[lid] : 0.f;
        float q2 = (lid < 8) ? rq[lid] : 0.f;
        #pragma unroll
        for (int o = 4; o > 0; o >>= 1) {
            s2 += __shfl_down_sync(0xffffffffu, s2, o);
            q2 += __shfl_down_sync(0xffffffffu, q2, o);
        }
        if (lid == 0) {
            float mean = s2 * (1.0f / DDIM);
            float var  = q2 * (1.0f / DDIM) - mean * mean;
            bmean = mean; brstd = rsqrtf(var + 1e-5f);
        }
    }
    __syncthreads();
    float mean = bmean, rstd = brstd;
    float4 gv = ((const float4*)gw)[tid];
    float4 sv = ((const float4*)sw)[tid];
    float o0 = gv.x * ((xv.x - mean) * rstd) + sv.x;
    float o1 = gv.y * ((xv.y - mean) * rstd) + sv.y;
    float o2 = gv.z * ((xv.z - mean) * rstd) + sv.z;
    float o3 = gv.w * ((xv.w - mean) * rstd) + sv.w;
    __nv_bfloat162 h2a, l2a, h2b, l2b;
    split2(o0, o1, h2a, l2a);
    split2(o2, o3, h2b, l2b);
    __nv_bfloat162* hp = (__nv_bfloat162*)(hi + (size_t)row * DDIM);
    __nv_bfloat162* lp = (__nv_bfloat162*)(lo + (size_t)row * DDIM);
    hp[2*tid] = h2a; hp[2*tid+1] = h2b;
    lp[2*tid] = l2a; lp[2*tid+1] = l2b;
}

// ---------------- weight transpose + split: W[K,N] -> out[N,K] hi/lo --------
__global__ __launch_bounds__(256) void cvt_t_kernel(
    const float* __restrict__ W, __nv_bfloat16* __restrict__ hi,
    __nv_bfloat16* __restrict__ lo, int K, int N)
{
    __shared__ float t[32][33];
    int n0 = blockIdx.x * 32, k0 = blockIdx.y * 32;
    int tx = threadIdx.x & 31, ty = threadIdx.x >> 5;   // 32 x 8
    #pragma unroll
    for (int i = 0; i < 4; i++)
        t[ty + 8*i][tx] = W[(size_t)(k0 + ty + 8*i) * N + n0 + tx];
    __syncthreads();
    #pragma unroll
    for (int i = 0; i < 4; i++) {
        float v = t[tx][ty + 8*i];
        size_t o = (size_t)(n0 + ty + 8*i) * K + k0 + tx;
        __nv_bfloat16 h = __float2bfloat16(v);
        hi[o] = h;
        lo[o] = __float2bfloat16(v - __bfloat162float(h));
    }
}

// ---------------- warp-MMA bf16 GEMM, fused 3-combo split --------------------
// C[M,N] = Ahi*Bhi + Ahi*Blo + Alo*Bhi. Single K loop; each BK=32 stage holds
// Ahi|Alo|Bhi|Blo tiles (32KB). 3 stages (96KB) -> 2 CTAs/SM. 8 warps (64x32).
#define TG_STAGE 32768
#define TG_NSTG 3
#define TG_SMEM (TG_NSTG * TG_STAGE)

template <bool BIAS, bool GELU, bool RES, bool SPL, bool QKV>
__global__ __launch_bounds__(256, 2) void tgemm_kernel(
    const __nv_bfloat16* __restrict__ Ahi, const __nv_bfloat16* __restrict__ Alo,
    const __nv_bfloat16* __restrict__ Bhi, const __nv_bfloat16* __restrict__ Blo,
    const float* __restrict__ bias, const float* __restrict__ res,
    float* __restrict__ C, __nv_bfloat16* __restrict__ Chi,
    __nv_bfloat16* __restrict__ Clo, int M, int N, int K)
{
    extern __shared__ char smem[];
    uint32_t sb = (uint32_t)__cvta_generic_to_shared(smem);
    int tid = threadIdx.x, lane = tid & 31, wid = tid >> 5;
    int wm = wid & 1, wn = wid >> 1;
    size_t row0 = (size_t)blockIdx.y * 128;
    size_t col0 = (size_t)blockIdx.x * 128;
    const int kc = K >> 5;

    float acc[4][4][4];
    #pragma unroll
    for (int i = 0; i < 4; i++)
        #pragma unroll
        for (int j = 0; j < 4; j++)
            #pragma unroll
            for (int r = 0; r < 4; r++) acc[i][j][r] = 0.f;

    int rowA = wm * 64 + (lane & 15);
    uint32_t xvA = (uint32_t)((rowA >> 1) & 3);
    int hiA = lane >> 4;
    int nrow = wn * 32 + (lane & 7) + ((lane & 16) >> 1);
    uint32_t xvB = (uint32_t)((nrow >> 1) & 3);
    int hiB = (lane >> 3) & 1;

    // per-thread load coords: 512 16B-ops per 8KB tile, 2 per thread per tile
    int lr0 = tid >> 1, lc0 = (tid & 1) << 1;     // rows 0..127, ck {0,2}
    auto tile_off = [&](int r, int ck) -> uint32_t {
        return (uint32_t)(r * 64 + ((ck ^ ((r >> 1) & 3)) << 4));
    };

    int stg_w = 0;   // write-stage rotator (avoids %3)
    auto load_chunk = [&](int c) {
        if (c < kc) {
            int k0 = c << 5;
            uint32_t st = sb + stg_w * TG_STAGE;
            const __nv_bfloat16* Ah = Ahi + (row0 + lr0) * K + k0;
            const __nv_bfloat16* Al = Alo + (row0 + lr0) * K + k0;
            const __nv_bfloat16* Bh = Bhi + (col0 + lr0) * K + k0;
            const __nv_bfloat16* Bl = Blo + (col0 + lr0) * K + k0;
            #pragma unroll
            for (int i = 0; i < 2; i++) {
                int ck = lc0 + i;
                uint32_t off = tile_off(lr0, ck);
                cp_async16(st + off,          Ah + ck * 8);
                cp_async16(st + 8192  + off,  Al + ck * 8);
                cp_async16(st + 16384 + off,  Bh + ck * 8);
                cp_async16(st + 24576 + off,  Bl + ck * 8);
            }
        }
        cp_commit();
        if (++stg_w == TG_NSTG) stg_w = 0;
    };

    load_chunk(0); load_chunk(1);

    int stg_r = 0;
    for (int c = 0; c < kc; c++) {
        cp_wait<1>();
        __syncthreads();
        load_chunk(c + 2);
        uint32_t st = sb + stg_r * TG_STAGE;
        if (++stg_r == TG_NSTG) stg_r = 0;
        #pragma unroll
        for (int ks = 0; ks < 2; ks++) {
            uint32_t ah[4][4], al[4][4], bh[4][2], bl[4][2];
            uint32_t ckA = ((uint32_t)(2*ks + hiA)) ^ xvA;
            uint32_t ckB = ((uint32_t)(2*ks + hiB)) ^ xvB;
            // hi x hi
            #pragma unroll
            for (int mt = 0; mt < 4; mt++) {
                uint32_t ro = (uint32_t)((rowA + mt*16) * 64) + (ckA << 4);
                ldsm4(ah[mt][0], ah[mt][1], ah[mt][2], ah[mt][3], st + ro);
            }
            #pragma unroll
            for (int np = 0; np < 2; np++) {
                uint32_t ro = (uint32_t)((nrow + np*16) * 64) + (ckB << 4);
                ldsm4(bh[np*2][0], bh[np*2][1], bh[np*2+1][0], bh[np*2+1][1],
                      st + 16384 + ro);
            }
            #pragma unroll
            for (int mt = 0; mt < 4; mt++)
                #pragma unroll
                for (int nt = 0; nt < 4; nt++)
                    mma16816(acc[mt][nt], ah[mt][0], ah[mt][1], ah[mt][2], ah[mt][3],
                             bh[nt][0], bh[nt][1]);
            // hi x lo
            #pragma unroll
            for (int np = 0; np < 2; np++) {
                uint32_t ro = (uint32_t)((nrow + np*16) * 64) + (ckB << 4);
                ldsm4(bl[np*2][0], bl[np*2][1], bl[np*2+1][0], bl[np*2+1][1],
                      st + 24576 + ro);
            }
            #pragma unroll
            for (int mt = 0; mt < 4; mt++)
                #pragma unroll
                for (int nt = 0; nt < 4; nt++)
                    mma16816(acc[mt][nt], ah[mt][0], ah[mt][1], ah[mt][2], ah[mt][3],
                             bl[nt][0], bl[nt][1]);
            // lo x hi
            #pragma unroll
            for (int mt = 0; mt < 4; mt++) {
                uint32_t ro = (uint32_t)((rowA + mt*16) * 64) + (ckA << 4);
                ldsm4(al[mt][0], al[mt][1], al[mt][2], al[mt][3], st + 8192 + ro);
            }
            #pragma unroll
            for (int mt = 0; mt < 4; mt++)
                #pragma unroll
                for (int nt = 0; nt < 4; nt++)
                    mma16816(acc[mt][nt], al[mt][0], al[mt][1], al[mt][2], al[mt][3],
                             bh[nt][0], bh[nt][1]);
        }
    }

    // ---------------- epilogue ----------------
    size_t rbase = row0 + wm*64 + (lane >> 2);
    size_t cbase = col0 + wn*32 + (lane & 3) * 2;
    #pragma unroll
    for (int mt = 0; mt < 4; mt++) {
        #pragma unroll
        for (int h = 0; h < 2; h++) {
            size_t r = rbase + mt*16 + h*8;
            #pragma unroll
            for (int nt = 0; nt < 4; nt++) {
                size_t cidx = cbase + nt*8;
                float v0 = acc[mt][nt][2*h], v1 = acc[mt][nt][2*h+1];
                if (BIAS) {
                    float2 bv = *(const float2*)(bias + cidx);
                    v0 += bv.x; v1 += bv.y;
                }
                if (GELU) { v0 = gelu_f(v0); v1 = gelu_f(v1); }
                if (RES) {
                    float2 rv = *(const float2*)(res + r * N + cidx);
                    v0 += rv.x; v1 += rv.y;
                }
                if (QKV) {
                    int sec = (int)(cidx >> 10);
                    int hh  = ((int)cidx >> 6) & 15;
                    int d   = (int)cidx & 63;
                    int b   = (int)(r >> 11);
                    int s   = (int)(r & 2047);
                    if (sec == 0) { v0 *= 0.125f; v1 *= 0.125f; }
                    __nv_bfloat16* dst = Chi + (size_t)sec * RR * DDIM +
                        (((size_t)(b * HH + hh) * SS + s) << 6) + d;
                    *(__nv_bfloat162*)dst =
                        __halves2bfloat162(__float2bfloat16(v0), __float2bfloat16(v1));
                } else if (SPL) {
                    __nv_bfloat162 h2, l2;
                    split2(v0, v1, h2, l2);
                    *(__nv_bfloat162*)(Chi + r * N + cidx) = h2;
                    *(__nv_bfloat162*)(Clo + r * N + cidx) = l2;
                } else {
                    float2 o; o.x = v0; o.y = v1;
                    *(float2*)(C + r * N + cidx) = o;
                }
            }
        }
    }
}

// ---------------- tensor-core flash attention --------------------------------
__global__ __launch_bounds__(128) void attn_kernel(
    const __nv_bfloat16* __restrict__ Qg, const __nv_bfloat16* __restrict__ Kg,
    const __nv_bfloat16* __restrict__ Vg, __nv_bfloat16* __restrict__ chi,
    __nv_bfloat16* __restrict__ clo)
{
    __shared__ __align__(128) char smQ[64 * 128];
    __shared__ __align__(128) char smK[2][64 * 128];
    __shared__ __align__(128) char smV[2][64 * 128];

    int qt = blockIdx.x, h = blockIdx.y, b = blockIdx.z;
    int tid = threadIdx.x, lane = tid & 31, w = tid >> 5;

    size_t headbase = (size_t)(b * HH + h) * SS * 64;
    const __nv_bfloat16* Qh = Qg + headbase + (size_t)qt * 64 * 64;
    const __nv_bfloat16* Kh = Kg + headbase;
    const __nv_bfloat16* Vh = Vg + headbase;

    uint32_t sq  = (uint32_t)__cvta_generic_to_shared(smQ);
    uint32_t sk[2] = { (uint32_t)__cvta_generic_to_shared(smK[0]),
                       (uint32_t)__cvta_generic_to_shared(smK[1]) };
    uint32_t sv[2] = { (uint32_t)__cvta_generic_to_shared(smV[0]),
                       (uint32_t)__cvta_generic_to_shared(smV[1]) };

    #pragma unroll
    for (int i = 0; i < 4; i++) {
        int idx = tid + 128 * i;
        int r = idx >> 3, c = idx & 7;
        cp_async16(sq + SWZ(r * 128 + c * 16), Qh + r * 64 + c * 8);
    }
    auto load_kv = [&](int kt) {
        int st = kt & 1;
        const __nv_bfloat16* Kc = Kh + (size_t)kt * 64 * 64;
        const __nv_bfloat16* Vc = Vh + (size_t)kt * 64 * 64;
        #pragma unroll
        for (int i = 0; i < 4; i++) {
            int idx = tid + 128 * i;
            int r = idx >> 3, c = idx & 7;
            uint32_t off = SWZ(r * 128 + c * 16);
            cp_async16(sk[st] + off, Kc + r * 64 + c * 8);
            cp_async16(sv[st] + off, Vc + r * 64 + c * 8);
        }
        cp_commit();
    };
    load_kv(0);
    cp_wait<0>();
    __syncthreads();

    uint32_t qf[4][4];
    {
        int rowA = w * 16 + (lane & 15);
        #pragma unroll
        for (int dt = 0; dt < 4; dt++)
            ldsm4(qf[dt][0], qf[dt][1], qf[dt][2], qf[dt][3],
                  sq + SWZ(rowA * 128 + dt * 32 + (lane >> 4) * 16));
    }

    float acc[8][4];
    #pragma unroll
    for (int nt = 0; nt < 8; nt++)
        #pragma unroll
        for (int r = 0; r < 4; r++) acc[nt][r] = 0.f;
    float mrow[2] = { -INFINITY, -INFINITY };
    float lrow[2] = { 0.f, 0.f };

    for (int kt = 0; kt <= qt; kt++) {
        int st = kt & 1;
        if (kt < qt) load_kv(kt + 1);
        if (kt < qt) cp_wait<1>(); else cp_wait<0>();
        __syncthreads();

        float s[8][4];
        #pragma unroll
        for (int nt = 0; nt < 8; nt++)
            #pragma unroll
            for (int r = 0; r < 4; r++) s[nt][r] = 0.f;
        int krow = (lane & 7) + ((lane & 16) >> 1);
        int khi  = (lane >> 3) & 1;
        #pragma unroll
        for (int dt = 0; dt < 4; dt++) {
            uint32_t kb[8][2];
            #pragma unroll
            for (int np = 0; np < 4; np++)
                ldsm4(kb[np*2][0], kb[np*2][1], kb[np*2+1][0], kb[np*2+1][1],
                      sk[st] + SWZ((np*16 + krow) * 128 + dt*32 + khi*16));
            #pragma unroll
            for (int nt = 0; nt < 8; nt++)
                mma16816(s[nt], qf[dt][0], qf[dt][1], qf[dt][2], qf[dt][3],
                         kb[nt][0], kb[nt][1]);
        }

        if (kt == qt) {
            #pragma unroll
            for (int nt = 0; nt < 8; nt++)
                #pragma unroll
                for (int r = 0; r < 4; r++) {
                    int qr = w*16 + (lane >> 2) + (r >> 1) * 8;
                    int kc2 = nt*8 + (lane & 3)*2 + (r & 1);
                    if (kc2 > qr) s[nt][r] = -INFINITY;
                }
        }

        #pragma unroll
        for (int hh = 0; hh < 2; hh++) {
            float mx = -INFINITY;
            #pragma unroll
            for (int nt = 0; nt < 8; nt++) {
                mx = fmaxf(mx, s[nt][2*hh]);
                mx = fmaxf(mx, s[nt][2*hh+1]);
            }
            mx = fmaxf(mx, __shfl_xor_sync(0xffffffffu, mx, 1));
            mx = fmaxf(mx, __shfl_xor_sync(0xffffffffu, mx, 2));
            float mnew = fmaxf(mrow[hh], mx);
            float corr = __expf(mrow[hh] - mnew);
            mrow[hh] = mnew;
            float psum = 0.f;
            #pragma unroll
            for (int nt = 0; nt < 8; nt++) {
                float p0 = __expf(s[nt][2*hh]   - mnew);
                float p1 = __expf(s[nt][2*hh+1] - mnew);
                s[nt][2*hh] = p0; s[nt][2*hh+1] = p1;
                psum += p0 + p1;
            }
            psum += __shfl_xor_sync(0xffffffffu, psum, 1);
            psum += __shfl_xor_sync(0xffffffffu, psum, 2);
            lrow[hh] = lrow[hh] * corr + psum;
            #pragma unroll
            for (int nt = 0; nt < 8; nt++) {
                acc[nt][2*hh]   *= corr;
                acc[nt][2*hh+1] *= corr;
            }
        }

        #pragma unroll
        for (int kt2 = 0; kt2 < 4; kt2++) {
            uint32_t a0 = packbf(s[2*kt2][0],   s[2*kt2][1]);
            uint32_t a1 = packbf(s[2*kt2][2],   s[2*kt2][3]);
            uint32_t a2 = packbf(s[2*kt2+1][0], s[2*kt2+1][1]);
            uint32_t a3 = packbf(s[2*kt2+1][2], s[2*kt2+1][3]);
            uint32_t vb[8][2];
            #pragma unroll
            for (int np = 0; np < 4; np++)
                ldsm4t(vb[np*2][0], vb[np*2][1], vb[np*2+1][0], vb[np*2+1][1],
                       sv[st] + SWZ((kt2*16 + (lane & 15)) * 128 + np*32 + (lane >> 4)*16));
            #pragma unroll
            for (int nt = 0; nt < 8; nt++)
                mma16816(acc[nt], a0, a1, a2, a3, vb[nt][0], vb[nt][1]);
        }
        __syncthreads();
    }

    #pragma unroll
    for (int hh = 0; hh < 2; hh++) {
        float inv = 1.f / lrow[hh];
        int row = qt*64 + w*16 + (lane >> 2) + hh*8;
        size_t obase = ((size_t)(b * SS + row)) * DDIM + h * 64;
        #pragma unroll
        for (int nt = 0; nt < 8; nt++) {
            int d = nt*8 + (lane & 3)*2;
            __nv_bfloat162 h2, l2;
            split2(acc[nt][2*hh] * inv, acc[nt][2*hh+1] * inv, h2, l2);
            *(__nv_bfloat162*)(chi + obase + d) = h2;
            *(__nv_bfloat162*)(clo + obase + d) = l2;
        }
    }
}

// ---------------- host launch ------------------------------------------------
extern "C" void kernel_launch(void* const* d_in, const int* in_sizes, int n_in,
                              void* d_out, int out_size)
{
    const float* x    = (const float*)d_in[0];
    const float* Wqkv = (const float*)d_in[1];
    const float* Wout = (const float*)d_in[2];
    const float* bout = (const float*)d_in[3];
    const float* W1   = (const float*)d_in[4];
    const float* b1   = (const float*)d_in[5];
    const float* W2   = (const float*)d_in[6];
    const float* b2   = (const float*)d_in[7];
    const float* g1   = (const float*)d_in[8];
    const float* s1   = (const float*)d_in[9];
    const float* g2   = (const float*)d_in[10];
    const float* s2   = (const float*)d_in[11];
    float* out = (float*)d_out;

    __nv_bfloat16 *pahi, *palo, *pmhi, *pmlo, *pbhi, *pblo;
    cudaGetSymbolAddress((void**)&pahi, g_ahi);
    cudaGetSymbolAddress((void**)&palo, g_alo);
    cudaGetSymbolAddress((void**)&pmhi, g_mhi);
    cudaGetSymbolAddress((void**)&pmlo, g_mlo);
    cudaGetSymbolAddress((void**)&pbhi, g_bhi);
    cudaGetSymbolAddress((void**)&pblo, g_blo);

    __nv_bfloat16* pQ = pmhi;                          // [B,H,S,64]
    __nv_bfloat16* pK = pmhi + (size_t)RR * DDIM;
    __nv_bfloat16* pV = pmhi + (size_t)2 * RR * DDIM;

    cudaFuncSetAttribute(tgemm_kernel<false,false,false,false,true>,
                         cudaFuncAttributeMaxDynamicSharedMemorySize, TG_SMEM);
    cudaFuncSetAttribute(tgemm_kernel<true,false,true,false,false>,
                         cudaFuncAttributeMaxDynamicSharedMemorySize, TG_SMEM);
    cudaFuncSetAttribute(tgemm_kernel<true,true,false,true,false>,
                         cudaFuncAttributeMaxDynamicSharedMemorySize, TG_SMEM);

    // 1. LN1 -> split(h)
    ln_split_kernel<<<RR, 256>>>(x, g1, s1, pahi, palo);
    // 2. qkv = h @ Wqkv -> bf16 Q(scaled)/K/V head-major
    cvt_t_kernel<<<dim3(3*DDIM/32, DDIM/32), 256>>>(Wqkv, pbhi, pblo, DDIM, 3*DDIM);
    tgemm_kernel<false,false,false,false,true><<<dim3(3*DDIM/128, RR/128), 256, TG_SMEM>>>(
        pahi, palo, pbhi, pblo, nullptr, nullptr, nullptr, pQ, nullptr,
        RR, 3*DDIM, DDIM);
    // 3. attention -> split(ctx)
    attn_kernel<<<dim3(SS/64, HH, BB), 128>>>(pQ, pK, pV, pahi, palo);
    // 4. out = x + ctx @ Wout + bout
    cvt_t_kernel<<<dim3(DDIM/32, DDIM/32), 256>>>(Wout, pbhi, pblo, DDIM, DDIM);
    tgemm_kernel<true,false,true,false,false><<<dim3(DDIM/128, RR/128), 256, TG_SMEM>>>(
        pahi, palo, pbhi, pblo, bout, x, out, nullptr, nullptr,
        RR, DDIM, DDIM);
    // 5. LN2 -> split(h)
    ln_split_kernel<<<RR, 256>>>(out, g2, s2, pahi, palo);
    // 6. mid = gelu(h @ W1 + b1) -> split(mid)
    cvt_t_kernel<<<dim3(4*DDIM/32, DDIM/32), 256>>>(W1, pbhi, pblo, DDIM, 4*DDIM);
    tgemm_kernel<true,true,false,true,false><<<dim3(4*DDIM/128, RR/128), 256, TG_SMEM>>>(
        pahi, palo, pbhi, pblo, b1, nullptr, nullptr, pmhi, pmlo,
        RR, 4*DDIM, DDIM);
    // 7. out = out + mid @ W2 + b2
    cvt_t_kernel<<<dim3(DDIM/32, 4*DDIM/32), 256>>>(W2, pbhi, pblo, 4*DDIM, DDIM);
    tgemm_kernel<true,false,true,false,false><<<dim3(DDIM/128, RR/128), 256, TG_SMEM>>>(
        pmhi, pmlo, pbhi, pblo, b2, out, out, nullptr, nullptr,
        RR, DDIM, 4*DDIM);
}